// round 13
// baseline (speedup 1.0000x reference)
#include <cuda_runtime.h>
#include <cuda_fp16.h>
#include <cstdint>

// ---------------------------------------------------------------------------
// QuantizedLMHead (sm_103 baseline ISA):
//   prep:  Wh = fp16((lx*lw)*Z_w)              -> g_Wx  [2048, 32000]
//          x -> xh + 2^-11*xl'  (scaled fp16 residual)
//          U -> Uh + 2^-11*Ul'  (scaled fp16 residual)
//   GEMM1: acc = xl'@Uh + xh@Ul'; acc *= 2^-11; acc += xh@Uh
//          + nearest-codebook quantize epilogue -> fp16 g_Aq
//   GEMM2: logits = A @ Wh (mma.sync m16n8k16, fp32 acc, K=2048)
//
// R12: ks-level fragment double-buffering (a0/a1, b0/b1) inside each kt so
// LDSM latency hides under the previous ks's 16 HMMAs. Same tile config as
// R11 (128x128 CTA, 8 warps 2x4, 3-stage, 2 CTAs/SM). MMA order unchanged
// -> bitwise-identical numerics.
// ---------------------------------------------------------------------------

#define D_DIM 2048
#define V_DIM 32000
#define N_TOK 4096
#define RES_SCALE 2048.0f
#define RES_INV   (1.0f / 2048.0f)

__device__ __align__(256) __half g_Aq[(size_t)N_TOK * D_DIM];   // 16.8 MB
__device__ __align__(256) __half g_Wx[(size_t)D_DIM * V_DIM];   // 131 MB
__device__ __align__(256) __half g_xh[(size_t)N_TOK * D_DIM];
__device__ __align__(256) __half g_xl[(size_t)N_TOK * D_DIM];   // scaled 2^11
__device__ __align__(256) __half g_Uh[(size_t)D_DIM * D_DIM];
__device__ __align__(256) __half g_Ul[(size_t)D_DIM * D_DIM];   // scaled 2^11

// ---------------- PTX helpers ----------------------------------------------
__device__ __forceinline__ uint32_t smem_u32(const void* p) {
    uint32_t a;
    asm("{ .reg .u64 t; cvta.to.shared.u64 t, %1; cvt.u32.u64 %0, t; }" : "=r"(a) : "l"(p));
    return a;
}
__device__ __forceinline__ void cp16(uint32_t dst, const void* src) {
    asm volatile("cp.async.cg.shared.global [%0], [%1], 16;" :: "r"(dst), "l"(src));
}
#define CP_COMMIT() asm volatile("cp.async.commit_group;" ::: "memory")
#define CP_WAIT1()  asm volatile("cp.async.wait_group 1;" ::: "memory")

__device__ __forceinline__ void ldsm4(uint32_t* r, uint32_t addr) {
    asm volatile("ldmatrix.sync.aligned.m8n8.x4.shared.b16 {%0,%1,%2,%3}, [%4];"
                 : "=r"(r[0]), "=r"(r[1]), "=r"(r[2]), "=r"(r[3]) : "r"(addr));
}
__device__ __forceinline__ void ldsm4t(uint32_t* r, uint32_t addr) {
    asm volatile("ldmatrix.sync.aligned.m8n8.x4.trans.shared.b16 {%0,%1,%2,%3}, [%4];"
                 : "=r"(r[0]), "=r"(r[1]), "=r"(r[2]), "=r"(r[3]) : "r"(addr));
}
__device__ __forceinline__ void mma16816(float* c, const uint32_t* a, uint32_t b0, uint32_t b1) {
    asm volatile("mma.sync.aligned.m16n8k16.row.col.f32.f16.f16.f32 "
                 "{%0,%1,%2,%3}, {%4,%5,%6,%7}, {%8,%9}, {%0,%1,%2,%3};"
                 : "+f"(c[0]), "+f"(c[1]), "+f"(c[2]), "+f"(c[3])
                 : "r"(a[0]), "r"(a[1]), "r"(a[2]), "r"(a[3]), "r"(b0), "r"(b1));
}

// ---------------------------------------------------------------------------
// Prep kernels (unchanged)
// ---------------------------------------------------------------------------
__global__ __launch_bounds__(256)
void wprep_kernel(const float* __restrict__ Zw, const float* __restrict__ lx,
                  const float* __restrict__ lw)
{
    const int idx = blockIdx.x * 256 + threadIdx.x;
    const int k   = idx / (V_DIM / 4);
    const int v4  = idx % (V_DIM / 4);
    const float coeff = __ldg(lx + k) * __ldg(lw + k);
    float4 w = *reinterpret_cast<const float4*>(Zw + (size_t)k * V_DIM + v4 * 4);
    __half h[4];
    h[0] = __float2half(coeff * w.x);
    h[1] = __float2half(coeff * w.y);
    h[2] = __float2half(coeff * w.z);
    h[3] = __float2half(coeff * w.w);
    *reinterpret_cast<uint2*>(g_Wx + (size_t)k * V_DIM + v4 * 4) =
        *reinterpret_cast<uint2*>(h);
}

template <int WHICH>   // 0: x -> g_xh/g_xl, 1: U -> g_Uh/g_Ul
__global__ __launch_bounds__(256)
void split_kernel(const float* __restrict__ src)
{
    __half* hi = (WHICH == 0) ? g_xh : g_Uh;
    __half* lo = (WHICH == 0) ? g_xl : g_Ul;
    const size_t i4 = ((size_t)blockIdx.x * 256 + threadIdx.x) * 4;
    float4 v = *reinterpret_cast<const float4*>(src + i4);
    __half h[4], l[4];
    h[0] = __float2half(v.x); l[0] = __float2half((v.x - __half2float(h[0])) * RES_SCALE);
    h[1] = __float2half(v.y); l[1] = __float2half((v.y - __half2float(h[1])) * RES_SCALE);
    h[2] = __float2half(v.z); l[2] = __float2half((v.z - __half2float(h[2])) * RES_SCALE);
    h[3] = __float2half(v.w); l[3] = __float2half((v.w - __half2float(h[3])) * RES_SCALE);
    *reinterpret_cast<uint2*>(hi + i4) = *reinterpret_cast<uint2*>(h);
    *reinterpret_cast<uint2*>(lo + i4) = *reinterpret_cast<uint2*>(l);
}

// ---------------------------------------------------------------------------
// GEMM tiling: 128(M)x128(N) CTA tile, BK=64, 3-stage cp.async, 2 CTAs/SM.
// 256 threads = 8 warps as 2(m)x4(n), warp tile 64x32.
// ---------------------------------------------------------------------------
#define BKK 64
#define STAGES 3
#define A_ROW_B 144                     // 64 fp16 + 8 pad
#define B_ROW_B 272                     // 128 fp16 + 8 pad (odd * 16B)
#define A_STG (128 * A_ROW_B)           // 18432
#define B_STG (64 * B_ROW_B)            // 17408
#define STG_B (A_STG + B_STG)           // 35840
#define SMEM_MMA (STAGES * STG_B)       // 107520 -> 2 CTAs/SM = 215040
#define NTHREADS 256

// Fragment load for one ks step into buffers A_/B_
#define LOADF(A_, B_, SA, SBB, KS)                                            \
    do {                                                                      \
        _Pragma("unroll")                                                     \
        for (int mi = 0; mi < 4; ++mi)                                        \
            ldsm4(A_[mi], (SA) + (a_row_l + mi * 16) * A_ROW_B                \
                              + (a_k_l + (KS) * 16) * 2);                     \
        _Pragma("unroll")                                                     \
        for (int ni2 = 0; ni2 < 2; ++ni2)                                     \
            ldsm4t(B_[ni2], (SBB) + (b_row_l + (KS) * 16) * B_ROW_B           \
                                 + (b_col_l + ni2 * 16) * 2);                 \
    } while (0)

// 16 mma for one ks step from buffers A_/B_
#define MMAF(A_, B_)                                                          \
    do {                                                                      \
        _Pragma("unroll")                                                     \
        for (int mi = 0; mi < 4; ++mi)                                        \
            _Pragma("unroll")                                                 \
            for (int ni = 0; ni < 4; ++ni)                                    \
                mma16816(acc[mi][ni], A_[mi], B_[ni >> 1][2 * (ni & 1)],      \
                         B_[ni >> 1][2 * (ni & 1) + 1]);                      \
    } while (0)

// Double-buffered kt body: LDSM of ks+1 hides under MMAs of ks.
#define KT_BODY_DB(SA, SBB)                                                   \
    do {                                                                      \
        uint32_t a0[4][4], a1[4][4], b0[2][4], b1[2][4];                      \
        LOADF(a0, b0, SA, SBB, 0);                                            \
        LOADF(a1, b1, SA, SBB, 1);                                            \
        MMAF(a0, b0);                                                         \
        LOADF(a0, b0, SA, SBB, 2);                                            \
        MMAF(a1, b1);                                                         \
        LOADF(a1, b1, SA, SBB, 3);                                            \
        MMAF(a0, b0);                                                         \
        MMAF(a1, b1);                                                         \
    } while (0)

// ---------------------------------------------------------------------------
// GEMM1 — scaled-residual 3-pass + quantize -> g_Aq.
// grid (N_TOK/128, D_DIM/128) = (32, 16). K_ext = 3*2048.
// ---------------------------------------------------------------------------
__global__ __launch_bounds__(NTHREADS, 2)
void gemm1_mma_kernel(const float* __restrict__ lx, const float* __restrict__ cb)
{
    extern __shared__ __align__(128) unsigned char sm1[];
    const uint32_t sb = smem_u32(sm1);
    const int tid  = threadIdx.x;
    const int lane = tid & 31;
    const int wid  = tid >> 5;
    const int wm   = wid >> 2;          // 0..1
    const int wn   = wid & 3;           // 0..3
    const int m0   = blockIdx.x * 128;
    const int n0   = blockIdx.y * 128;

    float acc[4][4][4];
    #pragma unroll
    for (int mi = 0; mi < 4; ++mi)
        #pragma unroll
        for (int ni = 0; ni < 4; ++ni)
            #pragma unroll
            for (int r = 0; r < 4; ++r) acc[mi][ni][r] = 0.0f;

    auto load_stage = [&](int kt, int slot) {
        const int p  = kt >> 5;            // pass: 0=lh, 1=hl, 2=hh
        const int kb = (kt & 31) * BKK;
        const __half* Ab = (p == 0) ? g_xl : g_xh;
        const __half* Bb = (p == 1) ? g_Ul : g_Uh;
        const uint32_t sa  = sb + slot * STG_B;
        const uint32_t sbB = sa + A_STG;
        #pragma unroll
        for (int i = 0; i < 4; ++i) {
            int cc = tid + i * NTHREADS;
            int row = cc >> 3, col = (cc & 7) * 8;
            cp16(sa + row * A_ROW_B + col * 2,
                 Ab + (size_t)(m0 + row) * D_DIM + kb + col);
        }
        #pragma unroll
        for (int i = 0; i < 4; ++i) {
            int cc = tid + i * NTHREADS;
            int row = cc >> 4, col = (cc & 15) * 8;
            cp16(sbB + row * B_ROW_B + col * 2,
                 Bb + (size_t)(kb + row) * D_DIM + n0 + col);
        }
        CP_COMMIT();
    };

    const int KT = 3 * (D_DIM / BKK);    // 96
    load_stage(0, 0);
    load_stage(1, 1);

    const int a_row_l = wm * 64 + (lane & 15);
    const int a_k_l   = (lane >> 4) * 8;
    const int b_row_l = (lane & 7) + ((lane >> 3) & 1) * 8;
    const int b_col_l = wn * 32 + ((lane >> 4) & 1) * 8;

    int slot = 0;
    for (int kt = 0; kt < KT; ++kt) {
        if (kt == 64) {   // acc holds 2^11*(lh+hl): rescale once before hh
            #pragma unroll
            for (int mi = 0; mi < 4; ++mi)
                #pragma unroll
                for (int ni = 0; ni < 4; ++ni)
                    #pragma unroll
                    for (int r = 0; r < 4; ++r)
                        acc[mi][ni][r] *= RES_INV;
        }

        CP_WAIT1();
        __syncthreads();
        const uint32_t sa  = sb + slot * STG_B;
        const uint32_t sbb = sa + A_STG;

        KT_BODY_DB(sa, sbb);

        if (kt + 2 < KT) load_stage(kt + 2, (slot + 2) % STAGES);
        else CP_COMMIT();
        slot = (slot + 1) % STAGES;
    }

    // epilogue: quantize s -> codebook value (tie -> lower index), store fp16
    float c[16];
    #pragma unroll
    for (int t = 0; t < 16; ++t) c[t] = cb[t];

    #pragma unroll
    for (int ni = 0; ni < 4; ++ni) {
        const int c0 = n0 + wn * 32 + ni * 8 + (lane & 3) * 2;
        float l0 = lx[c0], l1 = lx[c0 + 1];
        float s0 = (fabsf(l0) < 1e-8f) ? 1e-8f : l0;
        float s1 = (fabsf(l1) < 1e-8f) ? 1e-8f : l1;
        #pragma unroll
        for (int mi = 0; mi < 4; ++mi) {
            const int r0 = m0 + wm * 64 + mi * 16 + (lane >> 2);
            #pragma unroll
            for (int half_i = 0; half_i < 2; ++half_i) {
                float z0 = acc[mi][ni][2 * half_i]     / s0;
                float z1 = acc[mi][ni][2 * half_i + 1] / s1;
                float q0 = c[0], q1 = c[0];
                #pragma unroll
                for (int t = 0; t < 15; ++t) {
                    float mid = 0.5f * (c[t] + c[t + 1]);
                    q0 = (z0 > mid) ? c[t + 1] : q0;
                    q1 = (z1 > mid) ? c[t + 1] : q1;
                }
                __half2 hv = __halves2half2(__float2half(q0), __float2half(q1));
                *reinterpret_cast<uint32_t*>(
                    &g_Aq[(size_t)(r0 + 8 * half_i) * D_DIM + c0]) =
                    *reinterpret_cast<uint32_t*>(&hv);
            }
        }
    }
}

// ---------------------------------------------------------------------------
// GEMM2 — logits = A @ Wh. grid (N_TOK/128, V_DIM/128). K = 2048.
// ---------------------------------------------------------------------------
__global__ __launch_bounds__(NTHREADS, 2)
void gemm2_mma_kernel(float* __restrict__ C)
{
    extern __shared__ __align__(128) unsigned char sm2[];
    const uint32_t sb = smem_u32(sm2);
    const int tid  = threadIdx.x;
    const int lane = tid & 31;
    const int wid  = tid >> 5;
    const int wm   = wid >> 2;
    const int wn   = wid & 3;
    const int m0   = blockIdx.x * 128;
    const int n0   = blockIdx.y * 128;

    float acc[4][4][4];
    #pragma unroll
    for (int mi = 0; mi < 4; ++mi)
        #pragma unroll
        for (int ni = 0; ni < 4; ++ni)
            #pragma unroll
            for (int r = 0; r < 4; ++r) acc[mi][ni][r] = 0.0f;

    auto load_stage = [&](int kt, int slot) {
        const int kb = kt * BKK;
        const uint32_t sa  = sb + slot * STG_B;
        const uint32_t sbB = sa + A_STG;
        #pragma unroll
        for (int i = 0; i < 4; ++i) {
            int cc = tid + i * NTHREADS;
            int row = cc >> 3, col = (cc & 7) * 8;
            cp16(sa + row * A_ROW_B + col * 2,
                 g_Aq + (size_t)(m0 + row) * D_DIM + kb + col);
        }
        #pragma unroll
        for (int i = 0; i < 4; ++i) {
            int cc = tid + i * NTHREADS;
            int row = cc >> 4, col = (cc & 15) * 8;
            cp16(sbB + row * B_ROW_B + col * 2,
                 g_Wx + (size_t)(kb + row) * V_DIM + n0 + col);
        }
        CP_COMMIT();
    };

    const int KT = D_DIM / BKK;     // 32
    load_stage(0, 0);
    load_stage(1, 1);

    const int a_row_l = wm * 64 + (lane & 15);
    const int a_k_l   = (lane >> 4) * 8;
    const int b_row_l = (lane & 7) + ((lane >> 3) & 1) * 8;
    const int b_col_l = wn * 32 + ((lane >> 4) & 1) * 8;

    int slot = 0;
    for (int kt = 0; kt < KT; ++kt) {
        CP_WAIT1();
        __syncthreads();
        const uint32_t sa  = sb + slot * STG_B;
        const uint32_t sbb = sa + A_STG;

        KT_BODY_DB(sa, sbb);

        if (kt + 2 < KT) load_stage(kt + 2, (slot + 2) % STAGES);
        else CP_COMMIT();
        slot = (slot + 1) % STAGES;
    }

    #pragma unroll
    for (int mi = 0; mi < 4; ++mi) {
        const int row = m0 + wm * 64 + mi * 16 + (lane >> 2);
        #pragma unroll
        for (int ni = 0; ni < 4; ++ni) {
            const int col = n0 + wn * 32 + ni * 8 + (lane & 3) * 2;
            float2 v0 = make_float2(acc[mi][ni][0], acc[mi][ni][1]);
            float2 v1 = make_float2(acc[mi][ni][2], acc[mi][ni][3]);
            *reinterpret_cast<float2*>(C + (size_t)row * V_DIM + col) = v0;
            *reinterpret_cast<float2*>(C + (size_t)(row + 8) * V_DIM + col) = v1;
        }
    }
}

// ---------------------------------------------------------------------------
extern "C" void kernel_launch(void* const* d_in, const int* in_sizes, int n_in,
                              void* d_out, int out_size)
{
    const float* x  = (const float*)d_in[0];
    const float* U  = (const float*)d_in[1];
    const float* lx = (const float*)d_in[2];
    const float* lw = (const float*)d_in[3];
    const float* Zw = (const float*)d_in[4];
    const float* cb = (const float*)d_in[5];
    float* out = (float*)d_out;

    cudaFuncSetAttribute(gemm1_mma_kernel,
                         cudaFuncAttributeMaxDynamicSharedMemorySize, SMEM_MMA);
    cudaFuncSetAttribute(gemm2_mma_kernel,
                         cudaFuncAttributeMaxDynamicSharedMemorySize, SMEM_MMA);

    // prep
    wprep_kernel<<<(D_DIM * V_DIM / 4) / 256, 256>>>(Zw, lx, lw);
    split_kernel<0><<<((size_t)N_TOK * D_DIM / 4) / 256, 256>>>(x);
    split_kernel<1><<<((size_t)D_DIM * D_DIM / 4) / 256, 256>>>(U);

    // GEMM1 (scaled-residual 3-pass) + quantize -> g_Aq
    gemm1_mma_kernel<<<dim3(N_TOK / 128, D_DIM / 128), NTHREADS, SMEM_MMA>>>(lx, cb);

    // GEMM2 -> logits
    gemm2_mma_kernel<<<dim3(N_TOK / 128, V_DIM / 128), NTHREADS, SMEM_MMA>>>(out);
}

// round 14
// speedup vs baseline: 1.0339x; 1.0339x over previous
#include <cuda_runtime.h>
#include <cuda_fp16.h>
#include <cstdint>

// ---------------------------------------------------------------------------
// QuantizedLMHead (sm_103 baseline ISA):
//   prep (single merged kernel, 8 elems/thread):
//          Wh = fp16((lx*lw)*Z_w)              -> g_Wx  [2048, 32000]
//          x -> xh + 2^-11*xl'  (scaled fp16 residual)
//          U -> Uh + 2^-11*Ul'  (scaled fp16 residual)
//   GEMM1: acc = xl'@Uh + xh@Ul'; acc *= 2^-11; acc += xh@Uh
//          + nearest-codebook quantize epilogue -> fp16 g_Aq
//   GEMM2: logits = A @ Wh (mma.sync m16n8k16, fp32 acc, K=2048)
//
// R13: revert R12's fragment double-buffering (regressed; tensor% pinned at
// ~55% across all schedules -> HMMA-path ceiling). R11 mainloop restored.
// Single change: merged 1-launch prep kernel with 2xfloat4/thread.
// ---------------------------------------------------------------------------

#define D_DIM 2048
#define V_DIM 32000
#define N_TOK 4096
#define RES_SCALE 2048.0f
#define RES_INV   (1.0f / 2048.0f)

__device__ __align__(256) __half g_Aq[(size_t)N_TOK * D_DIM];   // 16.8 MB
__device__ __align__(256) __half g_Wx[(size_t)D_DIM * V_DIM];   // 131 MB
__device__ __align__(256) __half g_xh[(size_t)N_TOK * D_DIM];
__device__ __align__(256) __half g_xl[(size_t)N_TOK * D_DIM];   // scaled 2^11
__device__ __align__(256) __half g_Uh[(size_t)D_DIM * D_DIM];
__device__ __align__(256) __half g_Ul[(size_t)D_DIM * D_DIM];   // scaled 2^11

// ---------------- PTX helpers ----------------------------------------------
__device__ __forceinline__ uint32_t smem_u32(const void* p) {
    uint32_t a;
    asm("{ .reg .u64 t; cvta.to.shared.u64 t, %1; cvt.u32.u64 %0, t; }" : "=r"(a) : "l"(p));
    return a;
}
__device__ __forceinline__ void cp16(uint32_t dst, const void* src) {
    asm volatile("cp.async.cg.shared.global [%0], [%1], 16;" :: "r"(dst), "l"(src));
}
#define CP_COMMIT() asm volatile("cp.async.commit_group;" ::: "memory")
#define CP_WAIT1()  asm volatile("cp.async.wait_group 1;" ::: "memory")

__device__ __forceinline__ void ldsm4(uint32_t* r, uint32_t addr) {
    asm volatile("ldmatrix.sync.aligned.m8n8.x4.shared.b16 {%0,%1,%2,%3}, [%4];"
                 : "=r"(r[0]), "=r"(r[1]), "=r"(r[2]), "=r"(r[3]) : "r"(addr));
}
__device__ __forceinline__ void ldsm4t(uint32_t* r, uint32_t addr) {
    asm volatile("ldmatrix.sync.aligned.m8n8.x4.trans.shared.b16 {%0,%1,%2,%3}, [%4];"
                 : "=r"(r[0]), "=r"(r[1]), "=r"(r[2]), "=r"(r[3]) : "r"(addr));
}
__device__ __forceinline__ void mma16816(float* c, const uint32_t* a, uint32_t b0, uint32_t b1) {
    asm volatile("mma.sync.aligned.m16n8k16.row.col.f32.f16.f16.f32 "
                 "{%0,%1,%2,%3}, {%4,%5,%6,%7}, {%8,%9}, {%0,%1,%2,%3};"
                 : "+f"(c[0]), "+f"(c[1]), "+f"(c[2]), "+f"(c[3])
                 : "r"(a[0]), "r"(a[1]), "r"(a[2]), "r"(a[3]), "r"(b0), "r"(b1));
}

// ---------------------------------------------------------------------------
// Merged prep kernel: one launch, 8 elems/thread, block-range dispatch.
//   blocks [0, WPREP_BLKS)                      : Wh = fp16(coeff*Zw)
//   blocks [WPREP_BLKS, +SPLITX_BLKS)           : x -> xh/xl'
//   blocks [.., +SPLITU_BLKS)                   : U -> Uh/Ul'
// ---------------------------------------------------------------------------
#define WPREP_BLKS  ((D_DIM * V_DIM) / 8 / 256)          // 32000
#define SPLITX_BLKS (((size_t)N_TOK * D_DIM) / 8 / 256)  // 4096
#define SPLITU_BLKS (((size_t)D_DIM * D_DIM) / 8 / 256)  // 2048
#define PREP_BLKS   (WPREP_BLKS + SPLITX_BLKS + SPLITU_BLKS)

__device__ __forceinline__ void split8(const float* __restrict__ src, size_t i8,
                                       __half* __restrict__ hi, __half* __restrict__ lo)
{
    float4 v0 = *reinterpret_cast<const float4*>(src + i8);
    float4 v1 = *reinterpret_cast<const float4*>(src + i8 + 4);
    const float f[8] = {v0.x, v0.y, v0.z, v0.w, v1.x, v1.y, v1.z, v1.w};
    __half h[8], l[8];
    #pragma unroll
    for (int j = 0; j < 8; ++j) {
        h[j] = __float2half(f[j]);
        l[j] = __float2half((f[j] - __half2float(h[j])) * RES_SCALE);
    }
    *reinterpret_cast<uint4*>(hi + i8) = *reinterpret_cast<const uint4*>(h);
    *reinterpret_cast<uint4*>(lo + i8) = *reinterpret_cast<const uint4*>(l);
}

__global__ __launch_bounds__(256)
void prep_all_kernel(const float* __restrict__ x, const float* __restrict__ U,
                     const float* __restrict__ Zw, const float* __restrict__ lx,
                     const float* __restrict__ lw)
{
    const int b = blockIdx.x;
    if (b < WPREP_BLKS) {
        // V_DIM % 8 == 0 -> all 8 elems share one row k
        const size_t i8 = ((size_t)b * 256 + threadIdx.x) * 8;
        const int k = (int)(i8 / V_DIM);
        const float coeff = __ldg(lx + k) * __ldg(lw + k);
        float4 v0 = *reinterpret_cast<const float4*>(Zw + i8);
        float4 v1 = *reinterpret_cast<const float4*>(Zw + i8 + 4);
        __half h[8];
        h[0] = __float2half(coeff * v0.x); h[1] = __float2half(coeff * v0.y);
        h[2] = __float2half(coeff * v0.z); h[3] = __float2half(coeff * v0.w);
        h[4] = __float2half(coeff * v1.x); h[5] = __float2half(coeff * v1.y);
        h[6] = __float2half(coeff * v1.z); h[7] = __float2half(coeff * v1.w);
        *reinterpret_cast<uint4*>(g_Wx + i8) = *reinterpret_cast<const uint4*>(h);
    } else if (b < WPREP_BLKS + (int)SPLITX_BLKS) {
        const size_t i8 = ((size_t)(b - WPREP_BLKS) * 256 + threadIdx.x) * 8;
        split8(x, i8, g_xh, g_xl);
    } else {
        const size_t i8 = ((size_t)(b - WPREP_BLKS - SPLITX_BLKS) * 256 + threadIdx.x) * 8;
        split8(U, i8, g_Uh, g_Ul);
    }
}

// ---------------------------------------------------------------------------
// GEMM tiling: 128(M)x128(N) CTA tile, BK=64, 3-stage cp.async, 2 CTAs/SM.
// 256 threads = 8 warps as 2(m)x4(n), warp tile 64x32.  (R11-proven config)
// ---------------------------------------------------------------------------
#define BKK 64
#define STAGES 3
#define A_ROW_B 144                     // 64 fp16 + 8 pad
#define B_ROW_B 272                     // 128 fp16 + 8 pad (odd * 16B)
#define A_STG (128 * A_ROW_B)           // 18432
#define B_STG (64 * B_ROW_B)            // 17408
#define STG_B (A_STG + B_STG)           // 35840
#define SMEM_MMA (STAGES * STG_B)       // 107520 -> 2 CTAs/SM = 215040
#define NTHREADS 256

// ---------------------------------------------------------------------------
// GEMM1 — scaled-residual 3-pass + quantize -> g_Aq.
// grid (N_TOK/128, D_DIM/128) = (32, 16). K_ext = 3*2048.
// ---------------------------------------------------------------------------
__global__ __launch_bounds__(NTHREADS, 2)
void gemm1_mma_kernel(const float* __restrict__ lx, const float* __restrict__ cb)
{
    extern __shared__ __align__(128) unsigned char sm1[];
    const uint32_t sb = smem_u32(sm1);
    const int tid  = threadIdx.x;
    const int lane = tid & 31;
    const int wid  = tid >> 5;
    const int wm   = wid >> 2;          // 0..1
    const int wn   = wid & 3;           // 0..3
    const int m0   = blockIdx.x * 128;
    const int n0   = blockIdx.y * 128;

    float acc[4][4][4];
    #pragma unroll
    for (int mi = 0; mi < 4; ++mi)
        #pragma unroll
        for (int ni = 0; ni < 4; ++ni)
            #pragma unroll
            for (int r = 0; r < 4; ++r) acc[mi][ni][r] = 0.0f;

    auto load_stage = [&](int kt, int slot) {
        const int p  = kt >> 5;            // pass: 0=lh, 1=hl, 2=hh
        const int kb = (kt & 31) * BKK;
        const __half* Ab = (p == 0) ? g_xl : g_xh;
        const __half* Bb = (p == 1) ? g_Ul : g_Uh;
        const uint32_t sa  = sb + slot * STG_B;
        const uint32_t sbB = sa + A_STG;
        #pragma unroll
        for (int i = 0; i < 4; ++i) {
            int cc = tid + i * NTHREADS;
            int row = cc >> 3, col = (cc & 7) * 8;
            cp16(sa + row * A_ROW_B + col * 2,
                 Ab + (size_t)(m0 + row) * D_DIM + kb + col);
        }
        #pragma unroll
        for (int i = 0; i < 4; ++i) {
            int cc = tid + i * NTHREADS;
            int row = cc >> 4, col = (cc & 15) * 8;
            cp16(sbB + row * B_ROW_B + col * 2,
                 Bb + (size_t)(kb + row) * D_DIM + n0 + col);
        }
        CP_COMMIT();
    };

    const int KT = 3 * (D_DIM / BKK);    // 96
    load_stage(0, 0);
    load_stage(1, 1);

    const int a_row_l = wm * 64 + (lane & 15);
    const int a_k_l   = (lane >> 4) * 8;
    const int b_row_l = (lane & 7) + ((lane >> 3) & 1) * 8;
    const int b_col_l = wn * 32 + ((lane >> 4) & 1) * 8;

    int slot = 0;
    for (int kt = 0; kt < KT; ++kt) {
        if (kt == 64) {   // acc holds 2^11*(lh+hl): rescale once before hh
            #pragma unroll
            for (int mi = 0; mi < 4; ++mi)
                #pragma unroll
                for (int ni = 0; ni < 4; ++ni)
                    #pragma unroll
                    for (int r = 0; r < 4; ++r)
                        acc[mi][ni][r] *= RES_INV;
        }

        CP_WAIT1();
        __syncthreads();
        const uint32_t sa  = sb + slot * STG_B;
        const uint32_t sbb = sa + A_STG;

        #pragma unroll
        for (int ks = 0; ks < 4; ++ks) {
            uint32_t a[4][4], b[2][4];
            #pragma unroll
            for (int mi = 0; mi < 4; ++mi)
                ldsm4(a[mi], sa + (a_row_l + mi * 16) * A_ROW_B + (a_k_l + ks * 16) * 2);
            #pragma unroll
            for (int ni2 = 0; ni2 < 2; ++ni2)
                ldsm4t(b[ni2], sbb + (b_row_l + ks * 16) * B_ROW_B + (b_col_l + ni2 * 16) * 2);
            #pragma unroll
            for (int mi = 0; mi < 4; ++mi)
                #pragma unroll
                for (int ni = 0; ni < 4; ++ni)
                    mma16816(acc[mi][ni], a[mi], b[ni >> 1][2 * (ni & 1)],
                             b[ni >> 1][2 * (ni & 1) + 1]);
        }

        if (kt + 2 < KT) load_stage(kt + 2, (slot + 2) % STAGES);
        else CP_COMMIT();
        slot = (slot + 1) % STAGES;
    }

    // epilogue: quantize s -> codebook value (tie -> lower index), store fp16
    float c[16];
    #pragma unroll
    for (int t = 0; t < 16; ++t) c[t] = cb[t];

    #pragma unroll
    for (int ni = 0; ni < 4; ++ni) {
        const int c0 = n0 + wn * 32 + ni * 8 + (lane & 3) * 2;
        float l0 = lx[c0], l1 = lx[c0 + 1];
        float s0 = (fabsf(l0) < 1e-8f) ? 1e-8f : l0;
        float s1 = (fabsf(l1) < 1e-8f) ? 1e-8f : l1;
        #pragma unroll
        for (int mi = 0; mi < 4; ++mi) {
            const int r0 = m0 + wm * 64 + mi * 16 + (lane >> 2);
            #pragma unroll
            for (int half_i = 0; half_i < 2; ++half_i) {
                float z0 = acc[mi][ni][2 * half_i]     / s0;
                float z1 = acc[mi][ni][2 * half_i + 1] / s1;
                float q0 = c[0], q1 = c[0];
                #pragma unroll
                for (int t = 0; t < 15; ++t) {
                    float mid = 0.5f * (c[t] + c[t + 1]);
                    q0 = (z0 > mid) ? c[t + 1] : q0;
                    q1 = (z1 > mid) ? c[t + 1] : q1;
                }
                __half2 hv = __halves2half2(__float2half(q0), __float2half(q1));
                *reinterpret_cast<uint32_t*>(
                    &g_Aq[(size_t)(r0 + 8 * half_i) * D_DIM + c0]) =
                    *reinterpret_cast<uint32_t*>(&hv);
            }
        }
    }
}

// ---------------------------------------------------------------------------
// GEMM2 — logits = A @ Wh. grid (N_TOK/128, V_DIM/128). K = 2048.
// ---------------------------------------------------------------------------
__global__ __launch_bounds__(NTHREADS, 2)
void gemm2_mma_kernel(float* __restrict__ C)
{
    extern __shared__ __align__(128) unsigned char sm2[];
    const uint32_t sb = smem_u32(sm2);
    const int tid  = threadIdx.x;
    const int lane = tid & 31;
    const int wid  = tid >> 5;
    const int wm   = wid >> 2;
    const int wn   = wid & 3;
    const int m0   = blockIdx.x * 128;
    const int n0   = blockIdx.y * 128;

    float acc[4][4][4];
    #pragma unroll
    for (int mi = 0; mi < 4; ++mi)
        #pragma unroll
        for (int ni = 0; ni < 4; ++ni)
            #pragma unroll
            for (int r = 0; r < 4; ++r) acc[mi][ni][r] = 0.0f;

    auto load_stage = [&](int kt, int slot) {
        const int kb = kt * BKK;
        const uint32_t sa  = sb + slot * STG_B;
        const uint32_t sbB = sa + A_STG;
        #pragma unroll
        for (int i = 0; i < 4; ++i) {
            int cc = tid + i * NTHREADS;
            int row = cc >> 3, col = (cc & 7) * 8;
            cp16(sa + row * A_ROW_B + col * 2,
                 g_Aq + (size_t)(m0 + row) * D_DIM + kb + col);
        }
        #pragma unroll
        for (int i = 0; i < 4; ++i) {
            int cc = tid + i * NTHREADS;
            int row = cc >> 4, col = (cc & 15) * 8;
            cp16(sbB + row * B_ROW_B + col * 2,
                 g_Wx + (size_t)(kb + row) * V_DIM + n0 + col);
        }
        CP_COMMIT();
    };

    const int KT = D_DIM / BKK;     // 32
    load_stage(0, 0);
    load_stage(1, 1);

    const int a_row_l = wm * 64 + (lane & 15);
    const int a_k_l   = (lane >> 4) * 8;
    const int b_row_l = (lane & 7) + ((lane >> 3) & 1) * 8;
    const int b_col_l = wn * 32 + ((lane >> 4) & 1) * 8;

    int slot = 0;
    for (int kt = 0; kt < KT; ++kt) {
        CP_WAIT1();
        __syncthreads();
        const uint32_t sa  = sb + slot * STG_B;
        const uint32_t sbb = sa + A_STG;

        #pragma unroll
        for (int ks = 0; ks < 4; ++ks) {
            uint32_t a[4][4], b[2][4];
            #pragma unroll
            for (int mi = 0; mi < 4; ++mi)
                ldsm4(a[mi], sa + (a_row_l + mi * 16) * A_ROW_B + (a_k_l + ks * 16) * 2);
            #pragma unroll
            for (int ni2 = 0; ni2 < 2; ++ni2)
                ldsm4t(b[ni2], sbb + (b_row_l + ks * 16) * B_ROW_B + (b_col_l + ni2 * 16) * 2);
            #pragma unroll
            for (int mi = 0; mi < 4; ++mi)
                #pragma unroll
                for (int ni = 0; ni < 4; ++ni)
                    mma16816(acc[mi][ni], a[mi], b[ni >> 1][2 * (ni & 1)],
                             b[ni >> 1][2 * (ni & 1) + 1]);
        }

        if (kt + 2 < KT) load_stage(kt + 2, (slot + 2) % STAGES);
        else CP_COMMIT();
        slot = (slot + 1) % STAGES;
    }

    #pragma unroll
    for (int mi = 0; mi < 4; ++mi) {
        const int row = m0 + wm * 64 + mi * 16 + (lane >> 2);
        #pragma unroll
        for (int ni = 0; ni < 4; ++ni) {
            const int col = n0 + wn * 32 + ni * 8 + (lane & 3) * 2;
            float2 v0 = make_float2(acc[mi][ni][0], acc[mi][ni][1]);
            float2 v1 = make_float2(acc[mi][ni][2], acc[mi][ni][3]);
            *reinterpret_cast<float2*>(C + (size_t)row * V_DIM + col) = v0;
            *reinterpret_cast<float2*>(C + (size_t)(row + 8) * V_DIM + col) = v1;
        }
    }
}

// ---------------------------------------------------------------------------
extern "C" void kernel_launch(void* const* d_in, const int* in_sizes, int n_in,
                              void* d_out, int out_size)
{
    const float* x  = (const float*)d_in[0];
    const float* U  = (const float*)d_in[1];
    const float* lx = (const float*)d_in[2];
    const float* lw = (const float*)d_in[3];
    const float* Zw = (const float*)d_in[4];
    const float* cb = (const float*)d_in[5];
    float* out = (float*)d_out;

    cudaFuncSetAttribute(gemm1_mma_kernel,
                         cudaFuncAttributeMaxDynamicSharedMemorySize, SMEM_MMA);
    cudaFuncSetAttribute(gemm2_mma_kernel,
                         cudaFuncAttributeMaxDynamicSharedMemorySize, SMEM_MMA);

    // merged prep (one launch)
    prep_all_kernel<<<(unsigned)PREP_BLKS, 256>>>(x, U, Zw, lx, lw);

    // GEMM1 (scaled-residual 3-pass) + quantize -> g_Aq
    gemm1_mma_kernel<<<dim3(N_TOK / 128, D_DIM / 128), NTHREADS, SMEM_MMA>>>(lx, cb);

    // GEMM2 -> logits
    gemm2_mma_kernel<<<dim3(N_TOK / 128, V_DIM / 128), NTHREADS, SMEM_MMA>>>(out);
}

// round 15
// speedup vs baseline: 1.0683x; 1.0333x over previous
#include <cuda_runtime.h>
#include <cuda_fp16.h>
#include <cstdint>

// ---------------------------------------------------------------------------
// QuantizedLMHead (sm_103 baseline ISA):
//   prep A: x -> xh + 2^-11*xl', U -> Uh + 2^-11*Ul'   (small standalone)
//   GEMM1 (hybrid grid):
//     blocks [0,512)    : acc = xl'@Uh + xh@Ul'; *=2^-11; += xh@Uh
//                         + nearest-codebook quantize -> fp16 g_Aq
//     blocks [512,8512) : Wh = fp16((lx*lw)*Z_w) -> g_Wx   (backfills the
//                         GEMM's wave-2 tail; GEMM uses 2% DRAM, prep uses 0
//                         smem/tensor -> absorbed for free)
//   GEMM2: logits = A @ Wh (mma.sync m16n8k16, fp32 acc, K=2048)
// ---------------------------------------------------------------------------

#define D_DIM 2048
#define V_DIM 32000
#define N_TOK 4096
#define RES_SCALE 2048.0f
#define RES_INV   (1.0f / 2048.0f)

#define G1_TILES 512                 // 32 (m) x 16 (n)
#define WPREP_BLOCKS 8000            // 65,536,000 elems / (256 thr * 32 elems)

__device__ __align__(256) __half g_Aq[(size_t)N_TOK * D_DIM];   // 16.8 MB
__device__ __align__(256) __half g_Wx[(size_t)D_DIM * V_DIM];   // 131 MB
__device__ __align__(256) __half g_xh[(size_t)N_TOK * D_DIM];
__device__ __align__(256) __half g_xl[(size_t)N_TOK * D_DIM];   // scaled 2^11
__device__ __align__(256) __half g_Uh[(size_t)D_DIM * D_DIM];
__device__ __align__(256) __half g_Ul[(size_t)D_DIM * D_DIM];   // scaled 2^11

// ---------------- PTX helpers ----------------------------------------------
__device__ __forceinline__ uint32_t smem_u32(const void* p) {
    uint32_t a;
    asm("{ .reg .u64 t; cvta.to.shared.u64 t, %1; cvt.u32.u64 %0, t; }" : "=r"(a) : "l"(p));
    return a;
}
__device__ __forceinline__ void cp16(uint32_t dst, const void* src) {
    asm volatile("cp.async.cg.shared.global [%0], [%1], 16;" :: "r"(dst), "l"(src));
}
#define CP_COMMIT() asm volatile("cp.async.commit_group;" ::: "memory")
#define CP_WAIT1()  asm volatile("cp.async.wait_group 1;" ::: "memory")

__device__ __forceinline__ void ldsm4(uint32_t* r, uint32_t addr) {
    asm volatile("ldmatrix.sync.aligned.m8n8.x4.shared.b16 {%0,%1,%2,%3}, [%4];"
                 : "=r"(r[0]), "=r"(r[1]), "=r"(r[2]), "=r"(r[3]) : "r"(addr));
}
__device__ __forceinline__ void ldsm4t(uint32_t* r, uint32_t addr) {
    asm volatile("ldmatrix.sync.aligned.m8n8.x4.trans.shared.b16 {%0,%1,%2,%3}, [%4];"
                 : "=r"(r[0]), "=r"(r[1]), "=r"(r[2]), "=r"(r[3]) : "r"(addr));
}
__device__ __forceinline__ void mma16816(float* c, const uint32_t* a, uint32_t b0, uint32_t b1) {
    asm volatile("mma.sync.aligned.m16n8k16.row.col.f32.f16.f16.f32 "
                 "{%0,%1,%2,%3}, {%4,%5,%6,%7}, {%8,%9}, {%0,%1,%2,%3};"
                 : "+f"(c[0]), "+f"(c[1]), "+f"(c[2]), "+f"(c[3])
                 : "r"(a[0]), "r"(a[1]), "r"(a[2]), "r"(a[3]), "r"(b0), "r"(b1));
}

// ---------------------------------------------------------------------------
// Prep A kernel: x/U hi-lo splits only (needed BEFORE gemm1 starts).
// blocks [0, 4096): x (8.4M elems, 8/thread). blocks [4096, 6144): U.
// ---------------------------------------------------------------------------
#define SPLITX_BLKS 4096
#define SPLITU_BLKS 2048
#define SPLIT_BLKS  (SPLITX_BLKS + SPLITU_BLKS)

__device__ __forceinline__ void split8(const float* __restrict__ src, size_t i8,
                                       __half* __restrict__ hi, __half* __restrict__ lo)
{
    float4 v0 = *reinterpret_cast<const float4*>(src + i8);
    float4 v1 = *reinterpret_cast<const float4*>(src + i8 + 4);
    const float f[8] = {v0.x, v0.y, v0.z, v0.w, v1.x, v1.y, v1.z, v1.w};
    __half h[8], l[8];
    #pragma unroll
    for (int j = 0; j < 8; ++j) {
        h[j] = __float2half(f[j]);
        l[j] = __float2half((f[j] - __half2float(h[j])) * RES_SCALE);
    }
    *reinterpret_cast<uint4*>(hi + i8) = *reinterpret_cast<const uint4*>(h);
    *reinterpret_cast<uint4*>(lo + i8) = *reinterpret_cast<const uint4*>(l);
}

__global__ __launch_bounds__(256)
void prep_xu_kernel(const float* __restrict__ x, const float* __restrict__ U)
{
    const int b = blockIdx.x;
    if (b < SPLITX_BLKS) {
        const size_t i8 = ((size_t)b * 256 + threadIdx.x) * 8;
        split8(x, i8, g_xh, g_xl);
    } else {
        const size_t i8 = ((size_t)(b - SPLITX_BLKS) * 256 + threadIdx.x) * 8;
        split8(U, i8, g_Uh, g_Ul);
    }
}

// ---------------------------------------------------------------------------
// GEMM tiling: 128(M)x128(N) CTA tile, BK=64, 3-stage cp.async, 2 CTAs/SM.
// 256 threads = 8 warps as 2(m)x4(n), warp tile 64x32.  (R11-proven config)
// ---------------------------------------------------------------------------
#define BKK 64
#define STAGES 3
#define A_ROW_B 144                     // 64 fp16 + 8 pad
#define B_ROW_B 272                     // 128 fp16 + 8 pad (odd * 16B)
#define A_STG (128 * A_ROW_B)           // 18432
#define B_STG (64 * B_ROW_B)            // 17408
#define STG_B (A_STG + B_STG)           // 35840
#define SMEM_MMA (STAGES * STG_B)       // 107520 -> 2 CTAs/SM = 215040
#define NTHREADS 256

// ---------------------------------------------------------------------------
// GEMM1 hybrid — tiles + Wh-prep backfill blocks.
// grid 8512: b < 512 -> GEMM tile (bm = b&31, bn = b>>5), else Wh block.
// ---------------------------------------------------------------------------
__global__ __launch_bounds__(NTHREADS, 2)
void gemm1_mma_kernel(const float* __restrict__ lx, const float* __restrict__ cb,
                      const float* __restrict__ Zw, const float* __restrict__ lw)
{
    const int b = blockIdx.x;

    if (b >= G1_TILES) {
        // ---- Wh-prep backfill: 32 elems/thread, 8 independent float4 loads ----
        const uint32_t base = (uint32_t)(b - G1_TILES) * 8192u;
        #pragma unroll
        for (int i = 0; i < 8; ++i) {
            const uint32_t e = base + ((uint32_t)i * 256u + threadIdx.x) * 4u;
            const uint32_t k = e / (uint32_t)V_DIM;   // float4 never crosses a row (32000 % 4 == 0)
            const float coeff = __ldg(lx + k) * __ldg(lw + k);
            float4 v = *reinterpret_cast<const float4*>(Zw + e);
            __half h[4];
            h[0] = __float2half(coeff * v.x);
            h[1] = __float2half(coeff * v.y);
            h[2] = __float2half(coeff * v.z);
            h[3] = __float2half(coeff * v.w);
            *reinterpret_cast<uint2*>(g_Wx + e) = *reinterpret_cast<const uint2*>(h);
        }
        return;
    }

    // ---- GEMM tile path (byte-identical to R13) ----
    extern __shared__ __align__(128) unsigned char sm1[];
    const uint32_t sb = smem_u32(sm1);
    const int tid  = threadIdx.x;
    const int lane = tid & 31;
    const int wid  = tid >> 5;
    const int wm   = wid >> 2;          // 0..1
    const int wn   = wid & 3;           // 0..3
    const int m0   = (b & 31) * 128;
    const int n0   = (b >> 5) * 128;

    float acc[4][4][4];
    #pragma unroll
    for (int mi = 0; mi < 4; ++mi)
        #pragma unroll
        for (int ni = 0; ni < 4; ++ni)
            #pragma unroll
            for (int r = 0; r < 4; ++r) acc[mi][ni][r] = 0.0f;

    auto load_stage = [&](int kt, int slot) {
        const int p  = kt >> 5;            // pass: 0=lh, 1=hl, 2=hh
        const int kb = (kt & 31) * BKK;
        const __half* Ab = (p == 0) ? g_xl : g_xh;
        const __half* Bb = (p == 1) ? g_Ul : g_Uh;
        const uint32_t sa  = sb + slot * STG_B;
        const uint32_t sbB = sa + A_STG;
        #pragma unroll
        for (int i = 0; i < 4; ++i) {
            int cc = tid + i * NTHREADS;
            int row = cc >> 3, col = (cc & 7) * 8;
            cp16(sa + row * A_ROW_B + col * 2,
                 Ab + (size_t)(m0 + row) * D_DIM + kb + col);
        }
        #pragma unroll
        for (int i = 0; i < 4; ++i) {
            int cc = tid + i * NTHREADS;
            int row = cc >> 4, col = (cc & 15) * 8;
            cp16(sbB + row * B_ROW_B + col * 2,
                 Bb + (size_t)(kb + row) * D_DIM + n0 + col);
        }
        CP_COMMIT();
    };

    const int KT = 3 * (D_DIM / BKK);    // 96
    load_stage(0, 0);
    load_stage(1, 1);

    const int a_row_l = wm * 64 + (lane & 15);
    const int a_k_l   = (lane >> 4) * 8;
    const int b_row_l = (lane & 7) + ((lane >> 3) & 1) * 8;
    const int b_col_l = wn * 32 + ((lane >> 4) & 1) * 8;

    int slot = 0;
    for (int kt = 0; kt < KT; ++kt) {
        if (kt == 64) {   // acc holds 2^11*(lh+hl): rescale once before hh
            #pragma unroll
            for (int mi = 0; mi < 4; ++mi)
                #pragma unroll
                for (int ni = 0; ni < 4; ++ni)
                    #pragma unroll
                    for (int r = 0; r < 4; ++r)
                        acc[mi][ni][r] *= RES_INV;
        }

        CP_WAIT1();
        __syncthreads();
        const uint32_t sa  = sb + slot * STG_B;
        const uint32_t sbb = sa + A_STG;

        #pragma unroll
        for (int ks = 0; ks < 4; ++ks) {
            uint32_t a[4][4], bfr[2][4];
            #pragma unroll
            for (int mi = 0; mi < 4; ++mi)
                ldsm4(a[mi], sa + (a_row_l + mi * 16) * A_ROW_B + (a_k_l + ks * 16) * 2);
            #pragma unroll
            for (int ni2 = 0; ni2 < 2; ++ni2)
                ldsm4t(bfr[ni2], sbb + (b_row_l + ks * 16) * B_ROW_B + (b_col_l + ni2 * 16) * 2);
            #pragma unroll
            for (int mi = 0; mi < 4; ++mi)
                #pragma unroll
                for (int ni = 0; ni < 4; ++ni)
                    mma16816(acc[mi][ni], a[mi], bfr[ni >> 1][2 * (ni & 1)],
                             bfr[ni >> 1][2 * (ni & 1) + 1]);
        }

        if (kt + 2 < KT) load_stage(kt + 2, (slot + 2) % STAGES);
        else CP_COMMIT();
        slot = (slot + 1) % STAGES;
    }

    // epilogue: quantize s -> codebook value (tie -> lower index), store fp16
    float c[16];
    #pragma unroll
    for (int t = 0; t < 16; ++t) c[t] = cb[t];

    #pragma unroll
    for (int ni = 0; ni < 4; ++ni) {
        const int c0 = n0 + wn * 32 + ni * 8 + (lane & 3) * 2;
        float l0 = lx[c0], l1 = lx[c0 + 1];
        float s0 = (fabsf(l0) < 1e-8f) ? 1e-8f : l0;
        float s1 = (fabsf(l1) < 1e-8f) ? 1e-8f : l1;
        #pragma unroll
        for (int mi = 0; mi < 4; ++mi) {
            const int r0 = m0 + wm * 64 + mi * 16 + (lane >> 2);
            #pragma unroll
            for (int half_i = 0; half_i < 2; ++half_i) {
                float z0 = acc[mi][ni][2 * half_i]     / s0;
                float z1 = acc[mi][ni][2 * half_i + 1] / s1;
                float q0 = c[0], q1 = c[0];
                #pragma unroll
                for (int t = 0; t < 15; ++t) {
                    float mid = 0.5f * (c[t] + c[t + 1]);
                    q0 = (z0 > mid) ? c[t + 1] : q0;
                    q1 = (z1 > mid) ? c[t + 1] : q1;
                }
                __half2 hv = __halves2half2(__float2half(q0), __float2half(q1));
                *reinterpret_cast<uint32_t*>(
                    &g_Aq[(size_t)(r0 + 8 * half_i) * D_DIM + c0]) =
                    *reinterpret_cast<uint32_t*>(&hv);
            }
        }
    }
}

// ---------------------------------------------------------------------------
// GEMM2 — logits = A @ Wh. grid (N_TOK/128, V_DIM/128). K = 2048.
// ---------------------------------------------------------------------------
__global__ __launch_bounds__(NTHREADS, 2)
void gemm2_mma_kernel(float* __restrict__ C)
{
    extern __shared__ __align__(128) unsigned char sm2[];
    const uint32_t sb = smem_u32(sm2);
    const int tid  = threadIdx.x;
    const int lane = tid & 31;
    const int wid  = tid >> 5;
    const int wm   = wid >> 2;
    const int wn   = wid & 3;
    const int m0   = blockIdx.x * 128;
    const int n0   = blockIdx.y * 128;

    float acc[4][4][4];
    #pragma unroll
    for (int mi = 0; mi < 4; ++mi)
        #pragma unroll
        for (int ni = 0; ni < 4; ++ni)
            #pragma unroll
            for (int r = 0; r < 4; ++r) acc[mi][ni][r] = 0.0f;

    auto load_stage = [&](int kt, int slot) {
        const int kb = kt * BKK;
        const uint32_t sa  = sb + slot * STG_B;
        const uint32_t sbB = sa + A_STG;
        #pragma unroll
        for (int i = 0; i < 4; ++i) {
            int cc = tid + i * NTHREADS;
            int row = cc >> 3, col = (cc & 7) * 8;
            cp16(sa + row * A_ROW_B + col * 2,
                 g_Aq + (size_t)(m0 + row) * D_DIM + kb + col);
        }
        #pragma unroll
        for (int i = 0; i < 4; ++i) {
            int cc = tid + i * NTHREADS;
            int row = cc >> 4, col = (cc & 15) * 8;
            cp16(sbB + row * B_ROW_B + col * 2,
                 g_Wx + (size_t)(kb + row) * V_DIM + n0 + col);
        }
        CP_COMMIT();
    };

    const int KT = D_DIM / BKK;     // 32
    load_stage(0, 0);
    load_stage(1, 1);

    const int a_row_l = wm * 64 + (lane & 15);
    const int a_k_l   = (lane >> 4) * 8;
    const int b_row_l = (lane & 7) + ((lane >> 3) & 1) * 8;
    const int b_col_l = wn * 32 + ((lane >> 4) & 1) * 8;

    int slot = 0;
    for (int kt = 0; kt < KT; ++kt) {
        CP_WAIT1();
        __syncthreads();
        const uint32_t sa  = sb + slot * STG_B;
        const uint32_t sbb = sa + A_STG;

        #pragma unroll
        for (int ks = 0; ks < 4; ++ks) {
            uint32_t a[4][4], bfr[2][4];
            #pragma unroll
            for (int mi = 0; mi < 4; ++mi)
                ldsm4(a[mi], sa + (a_row_l + mi * 16) * A_ROW_B + (a_k_l + ks * 16) * 2);
            #pragma unroll
            for (int ni2 = 0; ni2 < 2; ++ni2)
                ldsm4t(bfr[ni2], sbb + (b_row_l + ks * 16) * B_ROW_B + (b_col_l + ni2 * 16) * 2);
            #pragma unroll
            for (int mi = 0; mi < 4; ++mi)
                #pragma unroll
                for (int ni = 0; ni < 4; ++ni)
                    mma16816(acc[mi][ni], a[mi], bfr[ni >> 1][2 * (ni & 1)],
                             bfr[ni >> 1][2 * (ni & 1) + 1]);
        }

        if (kt + 2 < KT) load_stage(kt + 2, (slot + 2) % STAGES);
        else CP_COMMIT();
        slot = (slot + 1) % STAGES;
    }

    #pragma unroll
    for (int mi = 0; mi < 4; ++mi) {
        const int row = m0 + wm * 64 + mi * 16 + (lane >> 2);
        #pragma unroll
        for (int ni = 0; ni < 4; ++ni) {
            const int col = n0 + wn * 32 + ni * 8 + (lane & 3) * 2;
            float2 v0 = make_float2(acc[mi][ni][0], acc[mi][ni][1]);
            float2 v1 = make_float2(acc[mi][ni][2], acc[mi][ni][3]);
            *reinterpret_cast<float2*>(C + (size_t)row * V_DIM + col) = v0;
            *reinterpret_cast<float2*>(C + (size_t)(row + 8) * V_DIM + col) = v1;
        }
    }
}

// ---------------------------------------------------------------------------
extern "C" void kernel_launch(void* const* d_in, const int* in_sizes, int n_in,
                              void* d_out, int out_size)
{
    const float* x  = (const float*)d_in[0];
    const float* U  = (const float*)d_in[1];
    const float* lx = (const float*)d_in[2];
    const float* lw = (const float*)d_in[3];
    const float* Zw = (const float*)d_in[4];
    const float* cb = (const float*)d_in[5];
    float* out = (float*)d_out;

    cudaFuncSetAttribute(gemm1_mma_kernel,
                         cudaFuncAttributeMaxDynamicSharedMemorySize, SMEM_MMA);
    cudaFuncSetAttribute(gemm2_mma_kernel,
                         cudaFuncAttributeMaxDynamicSharedMemorySize, SMEM_MMA);

    // 1) x/U hi-lo splits (gemm1 dependency; ~16 us)
    prep_xu_kernel<<<SPLIT_BLKS, 256>>>(x, U);

    // 2) GEMM1 tiles + Wh-prep backfill in one grid (Wh absorbed in wave tail)
    gemm1_mma_kernel<<<G1_TILES + WPREP_BLOCKS, NTHREADS, SMEM_MMA>>>(lx, cb, Zw, lw);

    // 3) GEMM2 -> logits
    gemm2_mma_kernel<<<dim3(N_TOK / 128, V_DIM / 128), NTHREADS, SMEM_MMA>>>(out);
}